// round 3
// baseline (speedup 1.0000x reference)
#include <cuda_runtime.h>
#include <cstdint>

#define NN 50000
#define EE 800000
#define IND 16
#define HD 128
#define WW 256          // fused width (policy 0..127, value 128..255)
#define TILE 32         // nodes per block in gemm2

// ---------------- device scratch (static, no allocation) ----------------
__device__ int   g_cnt[NN];
__device__ int   g_cur[NN];
__device__ int   g_off[NN + 1];
__device__ int   g_srcs[EE + NN];
__device__ float g_dis[NN];
__device__ float g_bufA[(size_t)NN * WW];   // gemm1 out / gemm2 out
__device__ float g_bufB[(size_t)NN * WW];   // spmm1 out

// ---------------- graph prep ----------------
__global__ void k_init() {
    int i = blockIdx.x * blockDim.x + threadIdx.x;
    if (i < NN) { g_cnt[i] = 0; g_cur[i] = 0; }
}

// edge_index is int32 (JAX default x64-disabled: randint(int64) -> int32)
__global__ void k_count(const int* __restrict__ ei) {
    int e = blockIdx.x * blockDim.x + threadIdx.x;
    if (e < EE) {
        int d = ei[EE + e];
        atomicAdd(&g_cnt[d], 1);
    }
}

// single-block exclusive scan of (cnt+1); also computes dis = rsqrt(deg)
__global__ void k_scan() {
    __shared__ int ssum[1024];
    int t = threadIdx.x;
    const int C = (NN + 1023) / 1024;   // 49
    int b = t * C;
    int e = b + C; if (e > NN) e = NN;
    if (b > NN) b = NN;
    int loc = 0;
    for (int i = b; i < e; i++) loc += g_cnt[i] + 1;
    ssum[t] = loc;
    __syncthreads();
    for (int off = 1; off < 1024; off <<= 1) {
        int v = (t >= off) ? ssum[t - off] : 0;
        __syncthreads();
        ssum[t] += v;
        __syncthreads();
    }
    int run = (t == 0) ? 0 : ssum[t - 1];
    for (int i = b; i < e; i++) {
        g_off[i] = run;
        int d = g_cnt[i] + 1;
        g_dis[i] = rsqrtf((float)d);
        run += d;
    }
    if (t == 1023) g_off[NN] = ssum[1023];
}

// fill CSR: edges via per-row cursor atomics, self-loop in last slot of each row
__global__ void k_fill(const int* __restrict__ ei) {
    int i = blockIdx.x * blockDim.x + threadIdx.x;
    if (i < EE) {
        int s = ei[i];
        int d = ei[EE + i];
        int pos = g_off[d] + atomicAdd(&g_cur[d], 1);
        g_srcs[pos] = s;
    } else if (i < EE + NN) {
        int n = i - EE;
        g_srcs[g_off[n + 1] - 1] = n;
    }
}

// ---------------- layer-1 GEMM: bufA = x @ [W_c1; W_v1]^T  (K=16) ----------------
__global__ void k_gemm1(const float* __restrict__ x,
                        const float* __restrict__ Wc1,
                        const float* __restrict__ Wv1) {
    __shared__ float xs[IND];
    int node = blockIdx.x, t = threadIdx.x;
    if (t < IND) xs[t] = x[node * IND + t];
    __syncthreads();
    const float* w = (t < HD) ? (Wc1 + t * IND) : (Wv1 + (t - HD) * IND);
    float a = 0.f;
#pragma unroll
    for (int k = 0; k < IND; k++) a = fmaf(__ldg(&w[k]), xs[k], a);
    g_bufA[(size_t)node * WW + t] = a;
}

// ---------------- SpMM1: bufB = relu(A_norm @ bufA + [b_c1; b_v1]) ----------------
__global__ void k_spmm1(const float* __restrict__ blo,
                        const float* __restrict__ bhi) {
    int node = blockIdx.x, t = threadIdx.x;
    float di = g_dis[node];
    int j = g_off[node], jend = g_off[node + 1];
    float acc = 0.f;
    for (; j < jend; j++) {
        int s = g_srcs[j];
        acc = fmaf(di * g_dis[s], g_bufA[(size_t)s * WW + t], acc);
    }
    float bias = (t < HD) ? __ldg(&blo[t]) : __ldg(&bhi[t - HD]);
    g_bufB[(size_t)node * WW + t] = fmaxf(acc + bias, 0.f);
}

// ---------------- layer-2 GEMM: bufA = bufB(split) @ [W_c2; W_v2]^T  (K=128) ------
// smem: only the 32-node h tile (32 KB). Weights stream via __ldg (L1-resident).
__global__ void __launch_bounds__(256, 4) k_gemm2(const float* __restrict__ Wc2,
                                                  const float* __restrict__ Wv2) {
    __shared__ float hs[TILE][WW];
    int t = threadIdx.x;
    int node0 = blockIdx.x * TILE;

    // load h tile (each thread one column across the 32 nodes)
#pragma unroll 4
    for (int n = 0; n < TILE; n++) {
        int node = node0 + n;
        hs[n][t] = (node < NN) ? g_bufB[(size_t)node * WW + t] : 0.f;
    }
    __syncthreads();

    int kb = (t & HD);              // 0 for policy cols, 128 for value cols
    const float4* wrow = (const float4*)((t < HD) ? (Wc2 + t * HD)
                                                  : (Wv2 + (t - HD) * HD));
    float acc[TILE];
#pragma unroll
    for (int n = 0; n < TILE; n++) acc[n] = 0.f;

#pragma unroll 2
    for (int k4 = 0; k4 < HD / 4; k4++) {
        float4 w4 = __ldg(&wrow[k4]);
#pragma unroll
        for (int n = 0; n < TILE; n++) {
            const float4 h4 = *(const float4*)&hs[n][kb + k4 * 4];
            acc[n] = fmaf(w4.x, h4.x, fmaf(w4.y, h4.y,
                      fmaf(w4.z, h4.z, fmaf(w4.w, h4.w, acc[n]))));
        }
    }

    for (int n = 0; n < TILE; n++) {
        int node = node0 + n;
        if (node < NN) g_bufA[(size_t)node * WW + t] = acc[n];
    }
}

// ---------------- SpMM2 + relu + heads ----------------
__global__ void k_spmm_head(const float* __restrict__ blo,
                            const float* __restrict__ bhi,
                            const float* __restrict__ Wp,
                            const float* __restrict__ Wvh,
                            const float* __restrict__ bp,
                            const float* __restrict__ bvh,
                            float* __restrict__ out) {
    __shared__ float red[256];
    int node = blockIdx.x, t = threadIdx.x;
    float di = g_dis[node];
    int j = g_off[node], jend = g_off[node + 1];
    float acc = 0.f;
    for (; j < jend; j++) {
        int s = g_srcs[j];
        acc = fmaf(di * g_dis[s], g_bufA[(size_t)s * WW + t], acc);
    }
    float bias = (t < HD) ? __ldg(&blo[t]) : __ldg(&bhi[t - HD]);
    float r = fmaxf(acc + bias, 0.f);
    float w = (t < HD) ? __ldg(&Wp[t]) : __ldg(&Wvh[t - HD]);
    red[t] = r * w;
    __syncthreads();
#pragma unroll
    for (int s2 = 64; s2 > 0; s2 >>= 1) {
        if ((t & 127) < s2) red[t] += red[t + s2];
        __syncthreads();
    }
    if (t == 0)   out[node]      = red[0]  + __ldg(&bp[0]);
    if (t == HD)  out[NN + node] = red[HD] + __ldg(&bvh[0]);
}

// ---------------- launch (kernel launches ONLY — capture/enforce safe) ----------
extern "C" void kernel_launch(void* const* d_in, const int* in_sizes, int n_in,
                              void* d_out, int out_size) {
    const float* x   = (const float*)d_in[0];
    const int*   ei  = (const int*)d_in[1];      // int32 edge_index [2, E]
    const float* Wc1 = (const float*)d_in[2];
    const float* bc1 = (const float*)d_in[3];
    const float* Wc2 = (const float*)d_in[4];
    const float* bc2 = (const float*)d_in[5];
    const float* Wp  = (const float*)d_in[6];
    const float* bp  = (const float*)d_in[7];
    const float* Wv1 = (const float*)d_in[8];
    const float* bv1 = (const float*)d_in[9];
    const float* Wv2 = (const float*)d_in[10];
    const float* bv2 = (const float*)d_in[11];
    const float* Wvh = (const float*)d_in[12];
    const float* bvh = (const float*)d_in[13];
    float* out = (float*)d_out;

    k_init <<<(NN + 255) / 256, 256>>>();
    k_count<<<(EE + 255) / 256, 256>>>(ei);
    k_scan <<<1, 1024>>>();
    k_fill <<<(EE + NN + 255) / 256, 256>>>(ei);

    k_gemm1<<<NN, 256>>>(x, Wc1, Wv1);
    k_spmm1<<<NN, 256>>>(bc1, bv1);
    k_gemm2<<<(NN + TILE - 1) / TILE, 256>>>(Wc2, Wv2);
    k_spmm_head<<<NN, 256>>>(bc2, bv2, Wp, Wvh, bp, bvh, out);
}

// round 4
// speedup vs baseline: 1.5503x; 1.5503x over previous
#include <cuda_runtime.h>
#include <cstdint>

#define NN 50000
#define EE 800000
#define IND 16
#define HD 128
#define WW 256          // fused width (policy 0..127, value 128..255)
#define TILE 32         // nodes per block in gemm2f
#define GP 36           // padded smem row (floats) for transposed tile

// ---------------- device scratch (static, no allocation) ----------------
__device__ int   g_cnt[NN];
__device__ int   g_cur[NN];
__device__ int   g_off[NN + 1];
__device__ int   g_srcs[EE + NN];
__device__ float g_dis[NN];
__device__ float g_agg16[(size_t)NN * IND];  // A_norm @ x
__device__ float g_h[(size_t)NN * WW];       // relu(agg16 @ W1^T + b1), fused width
__device__ float g_agg[(size_t)NN * WW];     // A_norm @ h

__device__ __forceinline__ unsigned long long ffma2(unsigned long long a,
                                                    unsigned long long b,
                                                    unsigned long long c) {
    unsigned long long d;
    asm("fma.rn.f32x2 %0, %1, %2, %3;" : "=l"(d) : "l"(a), "l"(b), "l"(c));
    return d;
}

// ---------------- graph prep ----------------
__global__ void k_init() {
    int i = blockIdx.x * blockDim.x + threadIdx.x;
    if (i < NN) { g_cnt[i] = 0; g_cur[i] = 0; }
}

__global__ void k_count(const int* __restrict__ ei) {
    int e = blockIdx.x * blockDim.x + threadIdx.x;
    if (e < EE) atomicAdd(&g_cnt[ei[EE + e]], 1);
}

// single-block exclusive scan of (cnt+1); also computes dis = rsqrt(deg)
__global__ void k_scan() {
    __shared__ int ssum[1024];
    int t = threadIdx.x;
    const int C = (NN + 1023) / 1024;   // 49
    int b = t * C;
    int e = b + C; if (e > NN) e = NN;
    if (b > NN) b = NN;
    int loc = 0;
    for (int i = b; i < e; i++) loc += g_cnt[i] + 1;
    ssum[t] = loc;
    __syncthreads();
    for (int off = 1; off < 1024; off <<= 1) {
        int v = (t >= off) ? ssum[t - off] : 0;
        __syncthreads();
        ssum[t] += v;
        __syncthreads();
    }
    int run = (t == 0) ? 0 : ssum[t - 1];
    for (int i = b; i < e; i++) {
        g_off[i] = run;
        int d = g_cnt[i] + 1;
        g_dis[i] = rsqrtf((float)d);
        run += d;
    }
    if (t == 1023) g_off[NN] = ssum[1023];
}

__global__ void k_fill(const int* __restrict__ ei) {
    int i = blockIdx.x * blockDim.x + threadIdx.x;
    if (i < EE) {
        int s = ei[i];
        int d = ei[EE + i];
        int pos = g_off[d] + atomicAdd(&g_cur[d], 1);
        g_srcs[pos] = s;
    } else if (i < EE + NN) {
        int n = i - EE;
        g_srcs[g_off[n + 1] - 1] = n;
    }
}

// ---------------- SpMM on x (16-wide): agg16 = A_norm @ x ----------------
// warp per node: 16 cols x 2 edge slots
__global__ void k_spmmx(const float* __restrict__ x) {
    int w = threadIdx.x >> 5, lane = threadIdx.x & 31;
    int node = blockIdx.x * 8 + w;
    if (node >= NN) return;
    int col = lane & 15, slot = lane >> 4;
    float di = g_dis[node];
    int jb = g_off[node], je = g_off[node + 1];
    float acc = 0.f;
    for (int j = jb + slot; j < je; j += 2) {
        int s = g_srcs[j];
        acc = fmaf(di * g_dis[s], x[s * IND + col], acc);
    }
    acc += __shfl_down_sync(0xffffffffu, acc, 16);
    if (slot == 0) g_agg16[node * IND + col] = acc;
}

// ---------------- dense layer 1: h = relu(agg16 @ [Wc1;Wv1]^T + b) -------
#define NPB1 8
__global__ void k_gemm1f(const float* __restrict__ Wc1, const float* __restrict__ Wv1,
                         const float* __restrict__ bc1, const float* __restrict__ bv1) {
    __shared__ float xs[NPB1][IND];
    int t = threadIdx.x;
    int node0 = blockIdx.x * NPB1;
    if (t < NPB1 * IND) {
        int n = t / IND, c = t % IND;
        int node = node0 + n;
        xs[n][c] = (node < NN) ? g_agg16[node * IND + c] : 0.f;
    }
    __syncthreads();
    const float4* wr = (const float4*)((t < HD) ? (Wc1 + t * IND)
                                                : (Wv1 + (t - HD) * IND));
    float4 w0 = __ldg(&wr[0]), w1 = __ldg(&wr[1]);
    float4 w2 = __ldg(&wr[2]), w3 = __ldg(&wr[3]);
    float bias = (t < HD) ? __ldg(&bc1[t]) : __ldg(&bv1[t - HD]);
#pragma unroll
    for (int n = 0; n < NPB1; n++) {
        int node = node0 + n;
        if (node >= NN) break;
        float a = bias;
        a = fmaf(w0.x, xs[n][0],  a); a = fmaf(w0.y, xs[n][1],  a);
        a = fmaf(w0.z, xs[n][2],  a); a = fmaf(w0.w, xs[n][3],  a);
        a = fmaf(w1.x, xs[n][4],  a); a = fmaf(w1.y, xs[n][5],  a);
        a = fmaf(w1.z, xs[n][6],  a); a = fmaf(w1.w, xs[n][7],  a);
        a = fmaf(w2.x, xs[n][8],  a); a = fmaf(w2.y, xs[n][9],  a);
        a = fmaf(w2.z, xs[n][10], a); a = fmaf(w2.w, xs[n][11], a);
        a = fmaf(w3.x, xs[n][12], a); a = fmaf(w3.y, xs[n][13], a);
        a = fmaf(w3.z, xs[n][14], a); a = fmaf(w3.w, xs[n][15], a);
        g_h[(size_t)node * WW + t] = fmaxf(a, 0.f);
    }
}

// ---------------- SpMM on h (256-wide): agg = A_norm @ h ----------------
// node per block; stage (src, norm) in smem, then high-MLP unrolled gather
__global__ void __launch_bounds__(256) k_spmmh() {
    __shared__ int   ss[256];
    __shared__ float sn[256];
    int node = blockIdx.x, t = threadIdx.x;
    float di = g_dis[node];
    int jb = g_off[node], je = g_off[node + 1];
    float acc = 0.f;
    for (int base = jb; base < je; base += 256) {
        int cnt = min(256, je - base);
        if (t < cnt) {
            int s = g_srcs[base + t];
            ss[t] = s;
            sn[t] = di * g_dis[s];
        }
        __syncthreads();
        int j = 0;
        for (; j + 4 <= cnt; j += 4) {
            int   s0 = ss[j],     s1 = ss[j + 1], s2 = ss[j + 2], s3 = ss[j + 3];
            float n0 = sn[j],     n1 = sn[j + 1], n2 = sn[j + 2], n3 = sn[j + 3];
            float v0 = g_h[(size_t)s0 * WW + t];
            float v1 = g_h[(size_t)s1 * WW + t];
            float v2 = g_h[(size_t)s2 * WW + t];
            float v3 = g_h[(size_t)s3 * WW + t];
            acc = fmaf(n0, v0, acc);
            acc = fmaf(n1, v1, acc);
            acc = fmaf(n2, v2, acc);
            acc = fmaf(n3, v3, acc);
        }
        for (; j < cnt; j++)
            acc = fmaf(sn[j], g_h[(size_t)ss[j] * WW + t], acc);
        __syncthreads();
    }
    g_agg[(size_t)node * WW + t] = acc;
}

// ---------------- dense layer 2 + heads ----------------
// z = relu(agg @ [Wc2;Wv2]^T + b2); out = z . [Wp | Wvh] + head bias
__global__ void __launch_bounds__(256, 3)
k_gemm2f(const float* __restrict__ Wc2, const float* __restrict__ Wv2,
         const float* __restrict__ bc2, const float* __restrict__ bv2,
         const float* __restrict__ Wp,  const float* __restrict__ Wvh,
         const float* __restrict__ bp,  const float* __restrict__ bvh,
         float* __restrict__ out) {
    __shared__ __align__(16) float hs[WW * GP];   // transposed tile [col][node]
    int t = threadIdx.x;
    int node0 = blockIdx.x * TILE;

    // load tile transposed: thread t = column t, write hs[t][n]
#pragma unroll 4
    for (int n = 0; n < TILE; n++) {
        int node = node0 + n;
        hs[t * GP + n] = (node < NN) ? g_agg[(size_t)node * WW + t] : 0.f;
    }
    __syncthreads();

    int kb = t & HD;  // policy cols read k 0..127, value cols 128..255
    const float4* w4p = (const float4*)((t < HD) ? (Wc2 + t * HD)
                                                 : (Wv2 + (t - HD) * HD));
    unsigned long long acc[16];
#pragma unroll
    for (int i = 0; i < 16; i++) acc[i] = 0ull;

#pragma unroll 1
    for (int k4 = 0; k4 < HD / 4; k4++) {
        float4 wq = __ldg(&w4p[k4]);
#pragma unroll
        for (int sub = 0; sub < 4; sub++) {
            float wk = (sub == 0) ? wq.x : (sub == 1) ? wq.y : (sub == 2) ? wq.z : wq.w;
            unsigned int wb = __float_as_uint(wk);
            unsigned long long w2;
            asm("mov.b64 %0, {%1, %2};" : "=l"(w2) : "r"(wb), "r"(wb));
            const float* row = &hs[(kb + k4 * 4 + sub) * GP];
#pragma unroll
            for (int np = 0; np < 8; np++) {
                ulonglong2 h2 = *(const ulonglong2*)&row[np * 4];
                acc[np * 2]     = ffma2(h2.x, w2, acc[np * 2]);
                acc[np * 2 + 1] = ffma2(h2.y, w2, acc[np * 2 + 1]);
            }
        }
    }
    __syncthreads();

    // epilogue: relu + bias, pre-multiply by head weight, store zs[col][node]
    float bias = (t < HD) ? __ldg(&bc2[t]) : __ldg(&bv2[t - HD]);
    float hw   = (t < HD) ? __ldg(&Wp[t])  : __ldg(&Wvh[t - HD]);
#pragma unroll
    for (int np = 0; np < 16; np++) {
        unsigned int lo, hi;
        asm("mov.b64 {%0, %1}, %2;" : "=r"(lo), "=r"(hi) : "l"(acc[np]));
        hs[t * GP + np * 2]     = fmaxf(__uint_as_float(lo) + bias, 0.f) * hw;
        hs[t * GP + np * 2 + 1] = fmaxf(__uint_as_float(hi) + bias, 0.f) * hw;
    }
    __syncthreads();

    // reduce: 64 tasks (32 nodes x 2 halves), 4 threads each sum 32 cols
    int task = t >> 2, l4 = t & 3;
    int n = task & 31, half = task >> 5;
    float s = 0.f;
#pragma unroll
    for (int i = 0; i < 32; i++) {
        int c = half * HD + l4 * 32 + i;
        s += hs[c * GP + n];
    }
    s += __shfl_down_sync(0xffffffffu, s, 1);
    s += __shfl_down_sync(0xffffffffu, s, 2);
    int node = node0 + n;
    if (l4 == 0 && node < NN) {
        if (half == 0) out[node]      = s + __ldg(&bp[0]);
        else           out[NN + node] = s + __ldg(&bvh[0]);
    }
}

// ---------------- launch (kernel launches ONLY) ----------------
extern "C" void kernel_launch(void* const* d_in, const int* in_sizes, int n_in,
                              void* d_out, int out_size) {
    const float* x   = (const float*)d_in[0];
    const int*   ei  = (const int*)d_in[1];      // int32 edge_index [2, E]
    const float* Wc1 = (const float*)d_in[2];
    const float* bc1 = (const float*)d_in[3];
    const float* Wc2 = (const float*)d_in[4];
    const float* bc2 = (const float*)d_in[5];
    const float* Wp  = (const float*)d_in[6];
    const float* bp  = (const float*)d_in[7];
    const float* Wv1 = (const float*)d_in[8];
    const float* bv1 = (const float*)d_in[9];
    const float* Wv2 = (const float*)d_in[10];
    const float* bv2 = (const float*)d_in[11];
    const float* Wvh = (const float*)d_in[12];
    const float* bvh = (const float*)d_in[13];
    float* out = (float*)d_out;

    k_init <<<(NN + 255) / 256, 256>>>();
    k_count<<<(EE + 255) / 256, 256>>>(ei);
    k_scan <<<1, 1024>>>();
    k_fill <<<(EE + NN + 255) / 256, 256>>>(ei);

    k_spmmx <<<(NN + 7) / 8, 256>>>(x);
    k_gemm1f<<<(NN + NPB1 - 1) / NPB1, 256>>>(Wc1, Wv1, bc1, bv1);
    k_spmmh <<<NN, 256>>>();
    k_gemm2f<<<(NN + TILE - 1) / TILE, 256>>>(Wc2, Wv2, bc2, bv2,
                                              Wp, Wvh, bp, bvh, out);
}

// round 5
// speedup vs baseline: 3.3470x; 2.1590x over previous
#include <cuda_runtime.h>
#include <cstdint>

#define NN 50000
#define EE 800000
#define IND 16
#define HD 128
#define WW 256          // fused width (policy 0..127, value 128..255)
#define TILE 32         // nodes per block in gemm2f
#define GP 36           // padded smem row (floats) for transposed tile
#define SCB 49          // scan blocks (49 * 1024 >= 50000)

// ---------------- device scratch (static, no allocation) ----------------
__device__ int   g_cnt[NN + 16];     // padded so int4 tail loads are safe
__device__ int   g_cur[NN];
__device__ int   g_off[NN + 1];
__device__ int   g_bsum[64];
__device__ int   g_boff[64];
__device__ int   g_srcs[EE + NN];
__device__ float g_dis[NN];
__device__ float g_agg16[(size_t)NN * IND];  // A_norm @ x
__device__ float g_h[(size_t)NN * WW];       // relu(agg16 @ W1^T + b1)
__device__ float g_agg[(size_t)NN * WW];     // A_norm @ h

__device__ __forceinline__ unsigned long long ffma2(unsigned long long a,
                                                    unsigned long long b,
                                                    unsigned long long c) {
    unsigned long long d;
    asm("fma.rn.f32x2 %0, %1, %2, %3;" : "=l"(d) : "l"(a), "l"(b), "l"(c));
    return d;
}

// ---------------- graph prep ----------------
__global__ void k_init() {
    int i = blockIdx.x * blockDim.x + threadIdx.x;
    if (i < NN) { g_cnt[i] = 0; g_cur[i] = 0; }
    else if (i < NN + 16) g_cnt[i] = 0;
}

__global__ void k_count(const int* __restrict__ ei) {
    int e = blockIdx.x * blockDim.x + threadIdx.x;
    if (e < EE) atomicAdd(&g_cnt[ei[EE + e]], 1);
}

// scan stage A: per-block sums of c[i] = cnt[i]+1 over 1024-elem ranges
__global__ void k_scanA() {
    __shared__ int sred[256];
    int b = blockIdx.x, t = threadIdx.x;
    int i0 = (b * 256 + t) * 4;
    int s = 0;
    if (i0 < NN) {
        int4 c = *(const int4*)&g_cnt[i0];
        s = c.x + c.y + c.z + c.w + 4;
    }
    sred[t] = s;
    __syncthreads();
#pragma unroll
    for (int off = 128; off > 0; off >>= 1) {
        if (t < off) sred[t] += sred[t + off];
        __syncthreads();
    }
    if (t == 0) g_bsum[b] = sred[0];
}

// scan stage B: exclusive scan of 49 block sums (1 block, 64 threads)
__global__ void k_scanB() {
    __shared__ int ss[64];
    int t = threadIdx.x;
    int v = (t < SCB) ? g_bsum[t] : 0;
    ss[t] = v;
    __syncthreads();
#pragma unroll
    for (int off = 1; off < 64; off <<= 1) {
        int u = (t >= off) ? ss[t - off] : 0;
        __syncthreads();
        ss[t] += u;
        __syncthreads();
    }
    g_boff[t] = ss[t] - v;           // exclusive
    if (t == 63) g_off[NN] = ss[63]; // total = EE + NN
}

// scan stage C: per-block rescan -> g_off + g_dis
__global__ void k_scanC() {
    __shared__ int ss[256];
    int b = blockIdx.x, t = threadIdx.x;
    int i0 = (b * 256 + t) * 4;
    int4 c = {0, 0, 0, 0};
    int s = 0;
    if (i0 < NN) {
        c = *(const int4*)&g_cnt[i0];
        c.x += 1; c.y += 1; c.z += 1; c.w += 1;
        s = c.x + c.y + c.z + c.w;
    }
    ss[t] = s;
    __syncthreads();
#pragma unroll
    for (int off = 1; off < 256; off <<= 1) {
        int u = (t >= off) ? ss[t - off] : 0;
        __syncthreads();
        ss[t] += u;
        __syncthreads();
    }
    int run = ss[t] - s + g_boff[b];
    if (i0 < NN) {
        g_off[i0]     = run; g_dis[i0]     = rsqrtf((float)c.x); run += c.x;
        g_off[i0 + 1] = run; g_dis[i0 + 1] = rsqrtf((float)c.y); run += c.y;
        g_off[i0 + 2] = run; g_dis[i0 + 2] = rsqrtf((float)c.z); run += c.z;
        g_off[i0 + 3] = run; g_dis[i0 + 3] = rsqrtf((float)c.w);
    }
}

__global__ void k_fill(const int* __restrict__ ei) {
    int i = blockIdx.x * blockDim.x + threadIdx.x;
    if (i < EE) {
        int s = ei[i];
        int d = ei[EE + i];
        int pos = g_off[d] + atomicAdd(&g_cur[d], 1);
        g_srcs[pos] = s;
    } else if (i < EE + NN) {
        int n = i - EE;
        g_srcs[g_off[n + 1] - 1] = n;
    }
}

// ---------------- SpMM on x (16-wide): agg16 = A_norm @ x ----------------
// warp per node: 16 cols x 2 edge slots
__global__ void k_spmmx(const float* __restrict__ x) {
    int w = threadIdx.x >> 5, lane = threadIdx.x & 31;
    int node = blockIdx.x * 8 + w;
    if (node >= NN) return;
    int col = lane & 15, slot = lane >> 4;
    float di = g_dis[node];
    int jb = g_off[node], je = g_off[node + 1];
    float acc = 0.f;
    int j = jb + slot;
    for (; j + 2 < je; j += 4) {           // 2 edges per slot in flight
        int s0 = g_srcs[j], s1 = g_srcs[j + 2];
        float n0 = di * g_dis[s0], n1 = di * g_dis[s1];
        float v0 = x[s0 * IND + col], v1 = x[s1 * IND + col];
        acc = fmaf(n0, v0, acc);
        acc = fmaf(n1, v1, acc);
    }
    for (; j < je; j += 2) {
        int s = g_srcs[j];
        acc = fmaf(di * g_dis[s], x[s * IND + col], acc);
    }
    acc += __shfl_down_sync(0xffffffffu, acc, 16);
    if (slot == 0) g_agg16[node * IND + col] = acc;
}

// ---------------- dense layer 1: h = relu(agg16 @ [Wc1;Wv1]^T + b) -------
#define NPB1 8
__global__ void k_gemm1f(const float* __restrict__ Wc1, const float* __restrict__ Wv1,
                         const float* __restrict__ bc1, const float* __restrict__ bv1) {
    __shared__ float xs[NPB1][IND];
    int t = threadIdx.x;
    int node0 = blockIdx.x * NPB1;
    if (t < NPB1 * IND) {
        int n = t / IND, c = t % IND;
        int node = node0 + n;
        xs[n][c] = (node < NN) ? g_agg16[node * IND + c] : 0.f;
    }
    __syncthreads();
    const float4* wr = (const float4*)((t < HD) ? (Wc1 + t * IND)
                                                : (Wv1 + (t - HD) * IND));
    float4 w0 = __ldg(&wr[0]), w1 = __ldg(&wr[1]);
    float4 w2 = __ldg(&wr[2]), w3 = __ldg(&wr[3]);
    float bias = (t < HD) ? __ldg(&bc1[t]) : __ldg(&bv1[t - HD]);
#pragma unroll
    for (int n = 0; n < NPB1; n++) {
        int node = node0 + n;
        if (node >= NN) break;
        float a = bias;
        a = fmaf(w0.x, xs[n][0],  a); a = fmaf(w0.y, xs[n][1],  a);
        a = fmaf(w0.z, xs[n][2],  a); a = fmaf(w0.w, xs[n][3],  a);
        a = fmaf(w1.x, xs[n][4],  a); a = fmaf(w1.y, xs[n][5],  a);
        a = fmaf(w1.z, xs[n][6],  a); a = fmaf(w1.w, xs[n][7],  a);
        a = fmaf(w2.x, xs[n][8],  a); a = fmaf(w2.y, xs[n][9],  a);
        a = fmaf(w2.z, xs[n][10], a); a = fmaf(w2.w, xs[n][11], a);
        a = fmaf(w3.x, xs[n][12], a); a = fmaf(w3.y, xs[n][13], a);
        a = fmaf(w3.z, xs[n][14], a); a = fmaf(w3.w, xs[n][15], a);
        g_h[(size_t)node * WW + t] = fmaxf(a, 0.f);
    }
}

// ---------------- SpMM on h (256-wide): agg = A_norm @ h ----------------
// WARP per node: lane owns 8 cols (2x float4); edges unrolled x2.
// No barriers, independent chain per warp -> latency-hiding, LTS-bound.
__global__ void __launch_bounds__(256) k_spmmh() {
    int w = threadIdx.x >> 5, lane = threadIdx.x & 31;
    int node = blockIdx.x * 8 + w;
    if (node >= NN) return;
    float di = g_dis[node];
    int jb = g_off[node], je = g_off[node + 1];
    const float* hp = g_h + (size_t)lane * 8;
    float4 acc0 = {0.f, 0.f, 0.f, 0.f};
    float4 acc1 = {0.f, 0.f, 0.f, 0.f};
    int j = jb;
    for (; j + 2 <= je; j += 2) {
        int s0 = g_srcs[j], s1 = g_srcs[j + 1];
        float n0 = di * g_dis[s0], n1 = di * g_dis[s1];
        const float4* r0 = (const float4*)(hp + (size_t)s0 * WW);
        const float4* r1 = (const float4*)(hp + (size_t)s1 * WW);
        float4 a0 = __ldg(&r0[0]), b0 = __ldg(&r0[1]);
        float4 a1 = __ldg(&r1[0]), b1 = __ldg(&r1[1]);
        acc0.x = fmaf(n0, a0.x, acc0.x); acc0.y = fmaf(n0, a0.y, acc0.y);
        acc0.z = fmaf(n0, a0.z, acc0.z); acc0.w = fmaf(n0, a0.w, acc0.w);
        acc1.x = fmaf(n0, b0.x, acc1.x); acc1.y = fmaf(n0, b0.y, acc1.y);
        acc1.z = fmaf(n0, b0.z, acc1.z); acc1.w = fmaf(n0, b0.w, acc1.w);
        acc0.x = fmaf(n1, a1.x, acc0.x); acc0.y = fmaf(n1, a1.y, acc0.y);
        acc0.z = fmaf(n1, a1.z, acc0.z); acc0.w = fmaf(n1, a1.w, acc0.w);
        acc1.x = fmaf(n1, b1.x, acc1.x); acc1.y = fmaf(n1, b1.y, acc1.y);
        acc1.z = fmaf(n1, b1.z, acc1.z); acc1.w = fmaf(n1, b1.w, acc1.w);
    }
    if (j < je) {
        int s = g_srcs[j];
        float n0 = di * g_dis[s];
        const float4* r0 = (const float4*)(hp + (size_t)s * WW);
        float4 a0 = __ldg(&r0[0]), b0 = __ldg(&r0[1]);
        acc0.x = fmaf(n0, a0.x, acc0.x); acc0.y = fmaf(n0, a0.y, acc0.y);
        acc0.z = fmaf(n0, a0.z, acc0.z); acc0.w = fmaf(n0, a0.w, acc0.w);
        acc1.x = fmaf(n0, b0.x, acc1.x); acc1.y = fmaf(n0, b0.y, acc1.y);
        acc1.z = fmaf(n0, b0.z, acc1.z); acc1.w = fmaf(n0, b0.w, acc1.w);
    }
    float4* outp = (float4*)(g_agg + (size_t)node * WW + lane * 8);
    outp[0] = acc0;
    outp[1] = acc1;
}

// ---------------- dense layer 2 + heads ----------------
__global__ void __launch_bounds__(256, 3)
k_gemm2f(const float* __restrict__ Wc2, const float* __restrict__ Wv2,
         const float* __restrict__ bc2, const float* __restrict__ bv2,
         const float* __restrict__ Wp,  const float* __restrict__ Wvh,
         const float* __restrict__ bp,  const float* __restrict__ bvh,
         float* __restrict__ out) {
    __shared__ __align__(16) float hs[WW * GP];   // transposed tile [col][node]
    int t = threadIdx.x;
    int node0 = blockIdx.x * TILE;

#pragma unroll 4
    for (int n = 0; n < TILE; n++) {
        int node = node0 + n;
        hs[t * GP + n] = (node < NN) ? g_agg[(size_t)node * WW + t] : 0.f;
    }
    __syncthreads();

    int kb = t & HD;
    const float4* w4p = (const float4*)((t < HD) ? (Wc2 + t * HD)
                                                 : (Wv2 + (t - HD) * HD));
    unsigned long long acc[16];
#pragma unroll
    for (int i = 0; i < 16; i++) acc[i] = 0ull;

#pragma unroll 1
    for (int k4 = 0; k4 < HD / 4; k4++) {
        float4 wq = __ldg(&w4p[k4]);
#pragma unroll
        for (int sub = 0; sub < 4; sub++) {
            float wk = (sub == 0) ? wq.x : (sub == 1) ? wq.y : (sub == 2) ? wq.z : wq.w;
            unsigned int wb = __float_as_uint(wk);
            unsigned long long w2;
            asm("mov.b64 %0, {%1, %2};" : "=l"(w2) : "r"(wb), "r"(wb));
            const float* row = &hs[(kb + k4 * 4 + sub) * GP];
#pragma unroll
            for (int np = 0; np < 8; np++) {
                ulonglong2 h2 = *(const ulonglong2*)&row[np * 4];
                acc[np * 2]     = ffma2(h2.x, w2, acc[np * 2]);
                acc[np * 2 + 1] = ffma2(h2.y, w2, acc[np * 2 + 1]);
            }
        }
    }
    __syncthreads();

    float bias = (t < HD) ? __ldg(&bc2[t]) : __ldg(&bv2[t - HD]);
    float hw   = (t < HD) ? __ldg(&Wp[t])  : __ldg(&Wvh[t - HD]);
#pragma unroll
    for (int np = 0; np < 16; np++) {
        unsigned int lo, hi;
        asm("mov.b64 {%0, %1}, %2;" : "=r"(lo), "=r"(hi) : "l"(acc[np]));
        hs[t * GP + np * 2]     = fmaxf(__uint_as_float(lo) + bias, 0.f) * hw;
        hs[t * GP + np * 2 + 1] = fmaxf(__uint_as_float(hi) + bias, 0.f) * hw;
    }
    __syncthreads();

    int task = t >> 2, l4 = t & 3;
    int n = task & 31, half = task >> 5;
    float s = 0.f;
#pragma unroll
    for (int i = 0; i < 32; i++) {
        int c = half * HD + l4 * 32 + i;
        s += hs[c * GP + n];
    }
    s += __shfl_down_sync(0xffffffffu, s, 1);
    s += __shfl_down_sync(0xffffffffu, s, 2);
    int node = node0 + n;
    if (l4 == 0 && node < NN) {
        if (half == 0) out[node]      = s + __ldg(&bp[0]);
        else           out[NN + node] = s + __ldg(&bvh[0]);
    }
}

// ---------------- launch (kernel launches ONLY) ----------------
extern "C" void kernel_launch(void* const* d_in, const int* in_sizes, int n_in,
                              void* d_out, int out_size) {
    const float* x   = (const float*)d_in[0];
    const int*   ei  = (const int*)d_in[1];      // int32 edge_index [2, E]
    const float* Wc1 = (const float*)d_in[2];
    const float* bc1 = (const float*)d_in[3];
    const float* Wc2 = (const float*)d_in[4];
    const float* bc2 = (const float*)d_in[5];
    const float* Wp  = (const float*)d_in[6];
    const float* bp  = (const float*)d_in[7];
    const float* Wv1 = (const float*)d_in[8];
    const float* bv1 = (const float*)d_in[9];
    const float* Wv2 = (const float*)d_in[10];
    const float* bv2 = (const float*)d_in[11];
    const float* Wvh = (const float*)d_in[12];
    const float* bvh = (const float*)d_in[13];
    float* out = (float*)d_out;

    k_init <<<(NN + 16 + 255) / 256, 256>>>();
    k_count<<<(EE + 255) / 256, 256>>>(ei);
    k_scanA<<<SCB, 256>>>();
    k_scanB<<<1, 64>>>();
    k_scanC<<<SCB, 256>>>();
    k_fill <<<(EE + NN + 255) / 256, 256>>>(ei);

    k_spmmx <<<(NN + 7) / 8, 256>>>(x);
    k_gemm1f<<<(NN + NPB1 - 1) / NPB1, 256>>>(Wc1, Wv1, bc1, bv1);
    k_spmmh <<<(NN + 7) / 8, 256>>>();
    k_gemm2f<<<(NN + TILE - 1) / TILE, 256>>>(Wc2, Wv2, bc2, bv2,
                                              Wp, Wvh, bp, bvh, out);
}

// round 6
// speedup vs baseline: 3.7379x; 1.1168x over previous
#include <cuda_runtime.h>
#include <cuda_fp16.h>
#include <cstdint>

#define NN 50000
#define EE 800000
#define IND 16
#define HD 128
#define WW 256          // fused width (policy 0..127, value 128..255)
#define TILE 32         // nodes per block in gemm2f
#define GP 36           // padded smem row (floats) for transposed tile
#define SCB 49          // scan blocks

// ---------------- device scratch (static, no allocation) ----------------
__device__ int    g_cnt[NN + 16];
__device__ int    g_cur[NN];
__device__ int    g_off[NN + 1];
__device__ int    g_bsum[64];
__device__ int    g_boff[64];
__device__ int    g_srcs[EE + NN];
__device__ float  g_dis[NN];
__device__ float  g_agg16[(size_t)NN * IND];   // A_norm @ x
__device__ __half g_h[(size_t)NN * WW];        // relu(agg16 @ W1^T + b1), fp16
__device__ float  g_agg[(size_t)NN * WW];      // A_norm @ h

__device__ __forceinline__ unsigned long long ffma2(unsigned long long a,
                                                    unsigned long long b,
                                                    unsigned long long c) {
    unsigned long long d;
    asm("fma.rn.f32x2 %0, %1, %2, %3;" : "=l"(d) : "l"(a), "l"(b), "l"(c));
    return d;
}

// ---------------- graph prep ----------------
__global__ void k_init() {
    int i = blockIdx.x * blockDim.x + threadIdx.x;
    if (i < NN) { g_cnt[i] = 0; g_cur[i] = 0; }
    else if (i < NN + 16) g_cnt[i] = 0;
}

__global__ void k_count(const int* __restrict__ ei) {
    int e = blockIdx.x * blockDim.x + threadIdx.x;
    if (e < EE) atomicAdd(&g_cnt[ei[EE + e]], 1);
}

__global__ void k_scanA() {
    __shared__ int sred[256];
    int b = blockIdx.x, t = threadIdx.x;
    int i0 = (b * 256 + t) * 4;
    int s = 0;
    if (i0 < NN) {
        int4 c = *(const int4*)&g_cnt[i0];
        s = c.x + c.y + c.z + c.w + 4;
    }
    sred[t] = s;
    __syncthreads();
#pragma unroll
    for (int off = 128; off > 0; off >>= 1) {
        if (t < off) sred[t] += sred[t + off];
        __syncthreads();
    }
    if (t == 0) g_bsum[b] = sred[0];
}

__global__ void k_scanB() {
    __shared__ int ss[64];
    int t = threadIdx.x;
    int v = (t < SCB) ? g_bsum[t] : 0;
    ss[t] = v;
    __syncthreads();
#pragma unroll
    for (int off = 1; off < 64; off <<= 1) {
        int u = (t >= off) ? ss[t - off] : 0;
        __syncthreads();
        ss[t] += u;
        __syncthreads();
    }
    g_boff[t] = ss[t] - v;
    if (t == 63) g_off[NN] = ss[63];
}

__global__ void k_scanC() {
    __shared__ int ss[256];
    int b = blockIdx.x, t = threadIdx.x;
    int i0 = (b * 256 + t) * 4;
    int4 c = {0, 0, 0, 0};
    int s = 0;
    if (i0 < NN) {
        c = *(const int4*)&g_cnt[i0];
        c.x += 1; c.y += 1; c.z += 1; c.w += 1;
        s = c.x + c.y + c.z + c.w;
    }
    ss[t] = s;
    __syncthreads();
#pragma unroll
    for (int off = 1; off < 256; off <<= 1) {
        int u = (t >= off) ? ss[t - off] : 0;
        __syncthreads();
        ss[t] += u;
        __syncthreads();
    }
    int run = ss[t] - s + g_boff[b];
    if (i0 < NN) {
        g_off[i0]     = run; g_dis[i0]     = rsqrtf((float)c.x); run += c.x;
        g_off[i0 + 1] = run; g_dis[i0 + 1] = rsqrtf((float)c.y); run += c.y;
        g_off[i0 + 2] = run; g_dis[i0 + 2] = rsqrtf((float)c.z); run += c.z;
        g_off[i0 + 3] = run; g_dis[i0 + 3] = rsqrtf((float)c.w);
    }
}

__global__ void k_fill(const int* __restrict__ ei) {
    int i = blockIdx.x * blockDim.x + threadIdx.x;
    if (i < EE) {
        int s = ei[i];
        int d = ei[EE + i];
        int pos = g_off[d] + atomicAdd(&g_cur[d], 1);
        g_srcs[pos] = s;
    } else if (i < EE + NN) {
        int n = i - EE;
        g_srcs[g_off[n + 1] - 1] = n;
    }
}

// ---------------- SpMM on x (16-wide): agg16 = A_norm @ x ----------------
__global__ void k_spmmx(const float* __restrict__ x) {
    int w = threadIdx.x >> 5, lane = threadIdx.x & 31;
    int node = blockIdx.x * 8 + w;
    if (node >= NN) return;
    int col = lane & 15, slot = lane >> 4;
    float di = g_dis[node];
    int jb = g_off[node], je = g_off[node + 1];
    float acc = 0.f;
    int j = jb + slot;
    for (; j + 2 < je; j += 4) {
        int s0 = g_srcs[j], s1 = g_srcs[j + 2];
        float n0 = di * g_dis[s0], n1 = di * g_dis[s1];
        float v0 = x[s0 * IND + col], v1 = x[s1 * IND + col];
        acc = fmaf(n0, v0, acc);
        acc = fmaf(n1, v1, acc);
    }
    for (; j < je; j += 2) {
        int s = g_srcs[j];
        acc = fmaf(di * g_dis[s], x[s * IND + col], acc);
    }
    acc += __shfl_down_sync(0xffffffffu, acc, 16);
    if (slot == 0) g_agg16[node * IND + col] = acc;
}

// ---------------- dense layer 1: h = relu(agg16 @ [Wc1;Wv1]^T + b) -> fp16 ----
#define NPB1 8
__global__ void k_gemm1f(const float* __restrict__ Wc1, const float* __restrict__ Wv1,
                         const float* __restrict__ bc1, const float* __restrict__ bv1) {
    __shared__ float xs[NPB1][IND];
    int t = threadIdx.x;
    int node0 = blockIdx.x * NPB1;
    if (t < NPB1 * IND) {
        int n = t / IND, c = t % IND;
        int node = node0 + n;
        xs[n][c] = (node < NN) ? g_agg16[node * IND + c] : 0.f;
    }
    __syncthreads();
    const float4* wr = (const float4*)((t < HD) ? (Wc1 + t * IND)
                                                : (Wv1 + (t - HD) * IND));
    float4 w0 = __ldg(&wr[0]), w1 = __ldg(&wr[1]);
    float4 w2 = __ldg(&wr[2]), w3 = __ldg(&wr[3]);
    float bias = (t < HD) ? __ldg(&bc1[t]) : __ldg(&bv1[t - HD]);
#pragma unroll
    for (int n = 0; n < NPB1; n++) {
        int node = node0 + n;
        if (node >= NN) break;
        float a = bias;
        a = fmaf(w0.x, xs[n][0],  a); a = fmaf(w0.y, xs[n][1],  a);
        a = fmaf(w0.z, xs[n][2],  a); a = fmaf(w0.w, xs[n][3],  a);
        a = fmaf(w1.x, xs[n][4],  a); a = fmaf(w1.y, xs[n][5],  a);
        a = fmaf(w1.z, xs[n][6],  a); a = fmaf(w1.w, xs[n][7],  a);
        a = fmaf(w2.x, xs[n][8],  a); a = fmaf(w2.y, xs[n][9],  a);
        a = fmaf(w2.z, xs[n][10], a); a = fmaf(w2.w, xs[n][11], a);
        a = fmaf(w3.x, xs[n][12], a); a = fmaf(w3.y, xs[n][13], a);
        a = fmaf(w3.z, xs[n][14], a); a = fmaf(w3.w, xs[n][15], a);
        g_h[(size_t)node * WW + t] = __float2half(fmaxf(a, 0.f));
    }
}

// ---------------- SpMM on h (256-wide, fp16 gather): agg = A_norm @ h -------
// WARP per node: lane owns 8 cols = one uint4 (8 halves) per edge. Unroll x4.
__device__ __forceinline__ void acc8(float* acc, float nw, uint4 v) {
    float2 p;
    p = __half22float2(*(const __half2*)&v.x);
    acc[0] = fmaf(nw, p.x, acc[0]); acc[1] = fmaf(nw, p.y, acc[1]);
    p = __half22float2(*(((const __half2*)&v.x) + 1));
    acc[2] = fmaf(nw, p.x, acc[2]); acc[3] = fmaf(nw, p.y, acc[3]);
    p = __half22float2(*(const __half2*)&v.z);
    acc[4] = fmaf(nw, p.x, acc[4]); acc[5] = fmaf(nw, p.y, acc[5]);
    p = __half22float2(*(((const __half2*)&v.z) + 1));
    acc[6] = fmaf(nw, p.x, acc[6]); acc[7] = fmaf(nw, p.y, acc[7]);
}

__global__ void __launch_bounds__(256) k_spmmh() {
    int w = threadIdx.x >> 5, lane = threadIdx.x & 31;
    int node = blockIdx.x * 8 + w;
    if (node >= NN) return;
    float di = g_dis[node];
    int jb = g_off[node], je = g_off[node + 1];
    const __half* hp = g_h + (size_t)lane * 8;
    float acc[8];
#pragma unroll
    for (int i = 0; i < 8; i++) acc[i] = 0.f;
    int j = jb;
    for (; j + 4 <= je; j += 4) {
        int s0 = g_srcs[j],     s1 = g_srcs[j + 1];
        int s2 = g_srcs[j + 2], s3 = g_srcs[j + 3];
        float n0 = di * g_dis[s0], n1 = di * g_dis[s1];
        float n2 = di * g_dis[s2], n3 = di * g_dis[s3];
        uint4 v0 = __ldg((const uint4*)(hp + (size_t)s0 * WW));
        uint4 v1 = __ldg((const uint4*)(hp + (size_t)s1 * WW));
        uint4 v2 = __ldg((const uint4*)(hp + (size_t)s2 * WW));
        uint4 v3 = __ldg((const uint4*)(hp + (size_t)s3 * WW));
        acc8(acc, n0, v0);
        acc8(acc, n1, v1);
        acc8(acc, n2, v2);
        acc8(acc, n3, v3);
    }
    for (; j < je; j++) {
        int s = g_srcs[j];
        float nw = di * g_dis[s];
        uint4 v = __ldg((const uint4*)(hp + (size_t)s * WW));
        acc8(acc, nw, v);
    }
    float4* outp = (float4*)(g_agg + (size_t)node * WW + lane * 8);
    outp[0] = make_float4(acc[0], acc[1], acc[2], acc[3]);
    outp[1] = make_float4(acc[4], acc[5], acc[6], acc[7]);
}

// ---------------- dense layer 2 + heads ----------------
__global__ void __launch_bounds__(256, 3)
k_gemm2f(const float* __restrict__ Wc2, const float* __restrict__ Wv2,
         const float* __restrict__ bc2, const float* __restrict__ bv2,
         const float* __restrict__ Wp,  const float* __restrict__ Wvh,
         const float* __restrict__ bp,  const float* __restrict__ bvh,
         float* __restrict__ out) {
    __shared__ __align__(16) float hs[WW * GP];   // transposed tile [col][node]
    int t = threadIdx.x;
    int node0 = blockIdx.x * TILE;

#pragma unroll 4
    for (int n = 0; n < TILE; n++) {
        int node = node0 + n;
        hs[t * GP + n] = (node < NN) ? g_agg[(size_t)node * WW + t] : 0.f;
    }
    __syncthreads();

    int kb = t & HD;
    const float4* w4p = (const float4*)((t < HD) ? (Wc2 + t * HD)
                                                 : (Wv2 + (t - HD) * HD));
    unsigned long long acc[16];
#pragma unroll
    for (int i = 0; i < 16; i++) acc[i] = 0ull;

#pragma unroll 1
    for (int k4 = 0; k4 < HD / 4; k4++) {
        float4 wq = __ldg(&w4p[k4]);
#pragma unroll
        for (int sub = 0; sub < 4; sub++) {
            float wk = (sub == 0) ? wq.x : (sub == 1) ? wq.y : (sub == 2) ? wq.z : wq.w;
            unsigned int wb = __float_as_uint(wk);
            unsigned long long w2;
            asm("mov.b64 %0, {%1, %2};" : "=l"(w2) : "r"(wb), "r"(wb));
            const float* row = &hs[(kb + k4 * 4 + sub) * GP];
#pragma unroll
            for (int np = 0; np < 8; np++) {
                ulonglong2 h2 = *(const ulonglong2*)&row[np * 4];
                acc[np * 2]     = ffma2(h2.x, w2, acc[np * 2]);
                acc[np * 2 + 1] = ffma2(h2.y, w2, acc[np * 2 + 1]);
            }
        }
    }
    __syncthreads();

    float bias = (t < HD) ? __ldg(&bc2[t]) : __ldg(&bv2[t - HD]);
    float hw   = (t < HD) ? __ldg(&Wp[t])  : __ldg(&Wvh[t - HD]);
#pragma unroll
    for (int np = 0; np < 16; np++) {
        unsigned int lo, hi;
        asm("mov.b64 {%0, %1}, %2;" : "=r"(lo), "=r"(hi) : "l"(acc[np]));
        hs[t * GP + np * 2]     = fmaxf(__uint_as_float(lo) + bias, 0.f) * hw;
        hs[t * GP + np * 2 + 1] = fmaxf(__uint_as_float(hi) + bias, 0.f) * hw;
    }
    __syncthreads();

    int task = t >> 2, l4 = t & 3;
    int n = task & 31, half = task >> 5;
    float s = 0.f;
#pragma unroll
    for (int i = 0; i < 32; i++) {
        int c = half * HD + l4 * 32 + i;
        s += hs[c * GP + n];
    }
    s += __shfl_down_sync(0xffffffffu, s, 1);
    s += __shfl_down_sync(0xffffffffu, s, 2);
    int node = node0 + n;
    if (l4 == 0 && node < NN) {
        if (half == 0) out[node]      = s + __ldg(&bp[0]);
        else           out[NN + node] = s + __ldg(&bvh[0]);
    }
}

// ---------------- launch (kernel launches ONLY) ----------------
extern "C" void kernel_launch(void* const* d_in, const int* in_sizes, int n_in,
                              void* d_out, int out_size) {
    const float* x   = (const float*)d_in[0];
    const int*   ei  = (const int*)d_in[1];
    const float* Wc1 = (const float*)d_in[2];
    const float* bc1 = (const float*)d_in[3];
    const float* Wc2 = (const float*)d_in[4];
    const float* bc2 = (const float*)d_in[5];
    const float* Wp  = (const float*)d_in[6];
    const float* bp  = (const float*)d_in[7];
    const float* Wv1 = (const float*)d_in[8];
    const float* bv1 = (const float*)d_in[9];
    const float* Wv2 = (const float*)d_in[10];
    const float* bv2 = (const float*)d_in[11];
    const float* Wvh = (const float*)d_in[12];
    const float* bvh = (const float*)d_in[13];
    float* out = (float*)d_out;

    k_init <<<(NN + 16 + 255) / 256, 256>>>();
    k_count<<<(EE + 255) / 256, 256>>>(ei);
    k_scanA<<<SCB, 256>>>();
    k_scanB<<<1, 64>>>();
    k_scanC<<<SCB, 256>>>();
    k_fill <<<(EE + NN + 255) / 256, 256>>>(ei);

    k_spmmx <<<(NN + 7) / 8, 256>>>(x);
    k_gemm1f<<<(NN + NPB1 - 1) / NPB1, 256>>>(Wc1, Wv1, bc1, bv1);
    k_spmmh <<<(NN + 7) / 8, 256>>>();
    k_gemm2f<<<(NN + TILE - 1) / TILE, 256>>>(Wc2, Wv2, bc2, bv2,
                                              Wp, Wvh, bp, bvh, out);
}